// round 3
// baseline (speedup 1.0000x reference)
#include <cuda_runtime.h>

// Problem constants (fixed by the reference: B=8, N=M=4096, C=3)
#define BATCH        8
#define NPTS         4096
#define SORT_THREADS 1024
#define SRCH_THREADS 256
#define NPART        (2 * BATCH * NPTS / 32)   // one partial per warp = 2048

// Scratch (no device allocs allowed): sorted-by-z copies of both sets, SoA-in-float4
__device__ float4 g_sorted[2][BATCH][NPTS];    // 1 MB
__device__ float  g_partial[NPART];

// Monotone float -> uint mapping for sorting
__device__ __forceinline__ unsigned int f2sortable(float f) {
    unsigned int u = __float_as_uint(f);
    return (u & 0x80000000u) ? ~u : (u | 0x80000000u);
}

// Bitonic sort of each (set, batch) point cloud by z coordinate.
// Key = sortable(z) in high 32 bits, original index in low 32 -> total order,
// fully deterministic. One 1024-thread block per cloud; 32 KB smem.
__global__ __launch_bounds__(SORT_THREADS)
void sort_kernel(const float* __restrict__ x, const float* __restrict__ y) {
    __shared__ unsigned long long s[NPTS];
    const int b   = blockIdx.x;
    const int set = blockIdx.y;
    const float* P = (set == 0 ? x : y) + (size_t)b * NPTS * 3;
    const int tid = threadIdx.x;

    for (int k = tid; k < NPTS; k += SORT_THREADS) {
        float z = P[3 * k + 2];
        s[k] = ((unsigned long long)f2sortable(z) << 32) | (unsigned)k;
    }
    __syncthreads();

    for (int size = 2; size <= NPTS; size <<= 1) {
        for (int stride = size >> 1; stride > 0; stride >>= 1) {
            #pragma unroll 2
            for (int t = tid; t < NPTS / 2; t += SORT_THREADS) {
                int i = 2 * t - (t & (stride - 1));
                int j = i + stride;
                bool asc = ((i & size) == 0);
                unsigned long long a = s[i], c = s[j];
                if (asc ? (a > c) : (a < c)) { s[i] = c; s[j] = a; }
            }
            __syncthreads();
        }
    }

    float4* out = g_sorted[set][b];
    for (int k = tid; k < NPTS; k += SORT_THREADS) {
        int idx = (int)(s[k] & 0xFFFFFFFFu);
        out[k] = make_float4(P[3 * idx], P[3 * idx + 1], P[3 * idx + 2], 0.0f);
    }
}

// Exact pruned NN search. One thread = one query (taken in z-sorted order, so
// neighboring lanes probe neighboring target windows -> L1 reuse + low
// divergence). Expand two pointers outward from the z insertion point; since
// d >= |dz| and dz is monotone outward, stop a side when its dz >= best.
__global__ __launch_bounds__(SRCH_THREADS)
void search_kernel() {
    const int b   = blockIdx.y;
    const int dir = blockIdx.z;
    const float4* __restrict__ Q = g_sorted[dir][b];
    const float4* __restrict__ T = g_sorted[1 - dir][b];

    const int i = blockIdx.x * SRCH_THREADS + threadIdx.x;
    const float4 q = Q[i];

    // Branchless lower_bound of q.z in T[].z (T ascending in z)
    int pos = 0;
    #pragma unroll
    for (int step = NPTS / 2; step > 0; step >>= 1)
        if (T[pos + step - 1].z < q.z) pos += step;
    int hi = (T[pos].z < q.z) ? pos + 1 : pos;   // q.z > all -> hi = NPTS
    int lo = hi - 1;

    float4 plo, phi;
    float dlo = 1e30f, dhi = 1e30f;
    if (lo >= 0)   { plo = T[lo]; dlo = q.z - plo.z; }   // >= 0
    if (hi < NPTS) { phi = T[hi]; dhi = phi.z - q.z; }   // >= 0

    float best = 1e30f;
    while (fminf(dlo, dhi) < best) {
        if (dlo < dhi) {
            float d = fabsf(q.x - plo.x) + fabsf(q.y - plo.y) + dlo;
            best = fminf(best, d);
            if (--lo >= 0) { plo = T[lo]; dlo = q.z - plo.z; }
            else           dlo = 1e30f;
        } else {
            float d = fabsf(q.x - phi.x) + fabsf(q.y - phi.y) + dhi;
            best = fminf(best, d);
            if (++hi < NPTS) { phi = T[hi]; dhi = phi.z - q.z; }
            else             dhi = 1e30f;
        }
    }

    // Deterministic per-warp sum of minima (order fixed by sorted layout)
    float s = best;
    #pragma unroll
    for (int o = 16; o > 0; o >>= 1)
        s += __shfl_down_sync(0xffffffffu, s, o);
    if ((threadIdx.x & 31) == 0) {
        int warp = (i >> 5) + (NPTS / 32) * (b + BATCH * dir);
        g_partial[warp] = s;
    }
}

// total = (sum of all 65536 minima) / (B*N)  ==  mean_x + mean_y  (N == M)
__global__ void chamfer_reduce_kernel(float* __restrict__ out) {
    __shared__ float warp_s[8];
    const int tid = threadIdx.x;          // 256 threads

    float s = 0.0f;
    #pragma unroll
    for (int k = 0; k < NPART / 256; k++)
        s += g_partial[tid + 256 * k];

    #pragma unroll
    for (int o = 16; o > 0; o >>= 1)
        s += __shfl_down_sync(0xffffffffu, s, o);
    if ((tid & 31) == 0) warp_s[tid >> 5] = s;
    __syncthreads();

    if (tid < 32) {
        float v = (tid < 8) ? warp_s[tid] : 0.0f;
        #pragma unroll
        for (int o = 4; o > 0; o >>= 1)
            v += __shfl_down_sync(0xffffffffu, v, o);
        if (tid == 0)
            out[0] = v * (1.0f / (float)(BATCH * NPTS));
    }
}

extern "C" void kernel_launch(void* const* d_in, const int* in_sizes, int n_in,
                              void* d_out, int out_size) {
    const float* x = (const float*)d_in[0];
    const float* y = (const float*)d_in[1];
    float* out = (float*)d_out;
    (void)in_sizes; (void)n_in; (void)out_size;

    dim3 sgrid(BATCH, 2);
    sort_kernel<<<sgrid, SORT_THREADS>>>(x, y);

    dim3 ggrid(NPTS / SRCH_THREADS, BATCH, 2);   // 16 x 8 x 2 = 256 blocks
    search_kernel<<<ggrid, SRCH_THREADS>>>();

    chamfer_reduce_kernel<<<1, 256>>>(out);
}

// round 4
// speedup vs baseline: 1.6479x; 1.6479x over previous
#include <cuda_runtime.h>

// Problem constants (fixed by the reference: B=8, N=M=4096, C=3)
#define BATCH   8
#define NPTS    4096
#define NBINS   128
#define ZMIN    (-4.6f)
#define ZSPAN   (9.2f)
#define BINW    (ZSPAN / NBINS)
#define INVW    (NBINS / ZSPAN)
#define BTH     128                       // bin-kernel threads
#define PTS_PER_TH (NPTS / BTH)           // 32
#define STH     256                       // search-kernel threads
#define NPART   (2 * BATCH * NPTS / 32)   // one partial per warp = 2048

// Scratch (no device allocs): points regrouped by z-slab, per-cloud bin offsets
__device__ float4 g_pts[2][BATCH][NPTS];          // 1 MB
__device__ int    g_binstart[2][BATCH][NBINS + 1];
__device__ float  g_partial[NPART];

__device__ __forceinline__ int zbin(float z) {
    int b = (int)((z - ZMIN) * INVW);
    return min(max(b, 0), NBINS - 1);
}

// Deterministic counting sort into z-slabs. One block per cloud.
// cnt[bin][thread] is column-private (no atomics); stable rank =
// binbase[bin] + prefix-over-threads + running count -> bitwise deterministic.
__global__ __launch_bounds__(BTH)
void bin_kernel(const float* __restrict__ x, const float* __restrict__ y) {
    __shared__ unsigned short cnt[NBINS][BTH];    // 32 KB
    __shared__ int rowtot[NBINS];
    __shared__ int base[NBINS + 1];

    const int b   = blockIdx.x;
    const int set = blockIdx.y;
    const float* P = (set == 0 ? x : y) + (size_t)b * NPTS * 3;
    const int t    = threadIdx.x;
    const int lane = t & 31, warp = t >> 5;
    const unsigned FULL = 0xffffffffu;

    // zero counters
    for (int k = t; k < NBINS * BTH / 2; k += BTH)
        ((unsigned*)cnt)[k] = 0;
    __syncthreads();

    // pass 1: histogram (thread t owns points [32t, 32t+32))
    #pragma unroll 4
    for (int k = 0; k < PTS_PER_TH; k++) {
        int idx = t * PTS_PER_TH + k;
        cnt[zbin(P[3 * idx + 2])][t]++;
    }
    __syncthreads();

    // exclusive prefix over threads within each bin row (warp w: rows w*32..)
    for (int r = warp * 32; r < warp * 32 + 32; r++) {
        int carry = 0;
        #pragma unroll
        for (int c = 0; c < BTH / 32; c++) {
            int col = c * 32 + lane;
            int v = cnt[r][col];
            int s = v;
            #pragma unroll
            for (int o = 1; o < 32; o <<= 1) {
                int n = __shfl_up_sync(FULL, s, o);
                if (lane >= o) s += n;
            }
            cnt[r][col] = (unsigned short)(s - v + carry);
            carry += __shfl_sync(FULL, s, 31);
        }
        if (lane == 0) rowtot[r] = carry;
    }
    __syncthreads();

    // exclusive scan over bins (warp 0)
    if (warp == 0) {
        int carry = 0;
        #pragma unroll
        for (int c = 0; c < NBINS / 32; c++) {
            int i = c * 32 + lane;
            int v = rowtot[i];
            int s = v;
            #pragma unroll
            for (int o = 1; o < 32; o <<= 1) {
                int n = __shfl_up_sync(FULL, s, o);
                if (lane >= o) s += n;
            }
            base[i] = s - v + carry;
            carry += __shfl_sync(FULL, s, 31);
        }
        if (lane == 0) base[NBINS] = NPTS;
    }
    __syncthreads();

    // pass 2: stable scatter
    float4* out = g_pts[set][b];
    #pragma unroll 4
    for (int k = 0; k < PTS_PER_TH; k++) {
        int idx = t * PTS_PER_TH + k;
        float px = P[3 * idx], py = P[3 * idx + 1], pz = P[3 * idx + 2];
        int bb = zbin(pz);
        int off = base[bb] + cnt[bb][t];
        cnt[bb][t]++;
        out[off] = make_float4(px, py, pz, 0.0f);
    }
    for (int i = t; i <= NBINS; i += BTH)
        g_binstart[set][b][i] = base[i];
}

__device__ __forceinline__ float l1d(float4 q, float4 p) {
    return fabsf(q.x - p.x) + fabsf(q.y - p.y) + fabsf(q.z - p.z);
}

// Exact pruned NN: warp scans whole z-slabs uniformly (broadcast float4 loads,
// unroll 4), expanding the slab range outward; a side stops when every lane's
// distance to that slab edge >= its current best (d >= |dz| bound -> exact).
__global__ __launch_bounds__(STH)
void search_kernel() {
    const int b = blockIdx.y, dir = blockIdx.z;
    const float4* __restrict__ Q = g_pts[dir][b];
    const float4* __restrict__ T = g_pts[1 - dir][b];
    const int*    __restrict__ bs = g_binstart[1 - dir][b];
    const unsigned FULL = 0xffffffffu;

    const int i = blockIdx.x * STH + threadIdx.x;
    const float4 q = Q[i];

    // warp's slab range (queries are z-binned -> lanes span 1-2 slabs)
    int mybin = zbin(q.z);
    int blo = mybin, bhi = mybin;
    #pragma unroll
    for (int o = 16; o > 0; o >>= 1) {
        blo = min(blo, __shfl_xor_sync(FULL, blo, o));
        bhi = max(bhi, __shfl_xor_sync(FULL, bhi, o));
    }

    float m0 = 1e30f, m1 = 1e30f, m2 = 1e30f, m3 = 1e30f;
    int s = bs[blo], e = bs[bhi + 1];

    for (;;) {
        // brute-force scan of [s, e): uniform, 4 independent loads in flight
        int idx = s;
        for (; idx + 4 <= e; idx += 4) {
            float4 p0 = T[idx], p1 = T[idx + 1], p2 = T[idx + 2], p3 = T[idx + 3];
            m0 = fminf(m0, l1d(q, p0));
            m1 = fminf(m1, l1d(q, p1));
            m2 = fminf(m2, l1d(q, p2));
            m3 = fminf(m3, l1d(q, p3));
        }
        for (; idx < e; idx++)
            m0 = fminf(m0, l1d(q, T[idx]));

        float best = fminf(fminf(m0, m1), fminf(m2, m3));
        bool wl = (blo > 0) && (q.z - (ZMIN + blo * BINW) < best);
        bool wr = (bhi < NBINS - 1) && ((ZMIN + (bhi + 1) * BINW) - q.z < best);
        unsigned ml = __ballot_sync(FULL, wl);
        unsigned mr = __ballot_sync(FULL, wr);
        if (!(ml | mr)) break;

        if (ml && mr)      { --blo; ++bhi; s = bs[blo]; /* scan both new slabs */
                             e = bs[blo + 1];
                             // left slab now; right handled next loop via range trick:
                             // fold right slab into this pass by scanning it too
                             int s2 = bs[bhi], e2 = bs[bhi + 1];
                             int j = s2;
                             for (; j + 4 <= e2; j += 4) {
                                 float4 p0 = T[j], p1 = T[j+1], p2 = T[j+2], p3 = T[j+3];
                                 m0 = fminf(m0, l1d(q, p0));
                                 m1 = fminf(m1, l1d(q, p1));
                                 m2 = fminf(m2, l1d(q, p2));
                                 m3 = fminf(m3, l1d(q, p3));
                             }
                             for (; j < e2; j++) m0 = fminf(m0, l1d(q, T[j])); }
        else if (ml)       { --blo; s = bs[blo]; e = bs[blo + 1]; }
        else               { ++bhi; s = bs[bhi]; e = bs[bhi + 1]; }
    }

    // deterministic per-warp sum (binned order is deterministic)
    float v = fminf(fminf(m0, m1), fminf(m2, m3));
    #pragma unroll
    for (int o = 16; o > 0; o >>= 1)
        v += __shfl_down_sync(FULL, v, o);
    if ((threadIdx.x & 31) == 0) {
        int w = (i >> 5) + (NPTS / 32) * (b + BATCH * dir);
        g_partial[w] = v;
    }
}

// total = (sum of all 65536 minima) / (B*N)  ==  mean_x + mean_y  (N == M)
__global__ void chamfer_reduce_kernel(float* __restrict__ out) {
    __shared__ float warp_s[8];
    const int tid = threadIdx.x;          // 256 threads

    float s = 0.0f;
    #pragma unroll
    for (int k = 0; k < NPART / 256; k++)
        s += g_partial[tid + 256 * k];

    #pragma unroll
    for (int o = 16; o > 0; o >>= 1)
        s += __shfl_down_sync(0xffffffffu, s, o);
    if ((tid & 31) == 0) warp_s[tid >> 5] = s;
    __syncthreads();

    if (tid < 32) {
        float v = (tid < 8) ? warp_s[tid] : 0.0f;
        #pragma unroll
        for (int o = 4; o > 0; o >>= 1)
            v += __shfl_down_sync(0xffffffffu, v, o);
        if (tid == 0)
            out[0] = v * (1.0f / (float)(BATCH * NPTS));
    }
}

extern "C" void kernel_launch(void* const* d_in, const int* in_sizes, int n_in,
                              void* d_out, int out_size) {
    const float* x = (const float*)d_in[0];
    const float* y = (const float*)d_in[1];
    float* out = (float*)d_out;
    (void)in_sizes; (void)n_in; (void)out_size;

    dim3 bgrid(BATCH, 2);
    bin_kernel<<<bgrid, BTH>>>(x, y);

    dim3 ggrid(NPTS / STH, BATCH, 2);     // 16 x 8 x 2 = 256 blocks
    search_kernel<<<ggrid, STH>>>();

    chamfer_reduce_kernel<<<1, 256>>>(out);
}

// round 5
// speedup vs baseline: 6.2075x; 3.7669x over previous
#include <cuda_runtime.h>

// Problem constants (fixed by the reference: B=8, N=M=4096, C=3)
#define BATCH   8
#define NPTS    4096
#define TILE    1024
#define THREADS 128
#define NBLK_X  (NPTS / THREADS)            // 32
#define NPART   (NBLK_X * BATCH * 2)        // 512 per-block partials

__device__ float g_partial[NPART];

// x - a  as  FFMA(a, imm(-1.0f), x): rt_SMSP=1 (2x FADD throughput).
// Literal immediate in the PTX pins the src1-imm encoding.
__device__ __forceinline__ float sub_via_ffma(float a, float x) {
    float r;
    asm("fma.rn.f32 %0, %1, 0fBF800000, %2;" : "=f"(r) : "f"(a), "f"(x));
    return r;
}

// One thread = one query point; y-tile staged through smem (AoS, as in R1).
// blockIdx.z = 0: queries=x targets=y; z=1: queries=y targets=x.
__global__ __launch_bounds__(THREADS)
void chamfer_pass_kernel(const float* __restrict__ x,
                         const float* __restrict__ y) {
    __shared__ float sh[TILE * 3];
    __shared__ float warp_s[THREADS / 32];

    const int b   = blockIdx.y;
    const int dir = blockIdx.z;
    const float* A    = dir == 0 ? x : y;
    const float* Bset = dir == 0 ? y : x;

    const int i = blockIdx.x * THREADS + threadIdx.x;
    const float* Ab = A    + ((size_t)b * NPTS + i) * 3;
    const float* Bb = Bset + (size_t)b * NPTS * 3;

    const float x0 = Ab[0], x1 = Ab[1], x2 = Ab[2];

    // 4 rotating accumulators break the FMNMX dependency chain
    float m0 = 1e30f, m1 = 1e30f, m2 = 1e30f, m3 = 1e30f;

    for (int t = 0; t < NPTS; t += TILE) {
        __syncthreads();
        {
            const float4* src = (const float4*)(Bb + t * 3);
            float4*       dst = (float4*)sh;
            #pragma unroll
            for (int k = threadIdx.x; k < TILE * 3 / 4; k += THREADS)
                dst[k] = src[k];
        }
        __syncthreads();

        #pragma unroll 2
        for (int j = 0; j < TILE; j += 4) {
            const float* p = sh + 3 * j;
            // All lanes read the same smem addresses -> broadcast, no conflicts
            float a0 = p[0],  a1 = p[1],  a2 = p[2];
            float b0 = p[3],  b1 = p[4],  b2 = p[5];
            float c0 = p[6],  c1 = p[7],  c2 = p[8];
            float e0 = p[9],  e1 = p[10], e2 = p[11];

            // 3x FFMA-imm (rt1) + 2x FADD with |.| input modifiers (rt2)
            float sA0 = sub_via_ffma(a0, x0);
            float sA1 = sub_via_ffma(a1, x1);
            float sA2 = sub_via_ffma(a2, x2);
            float dA  = (fabsf(sA0) + fabsf(sA1)) + fabsf(sA2);

            float sB0 = sub_via_ffma(b0, x0);
            float sB1 = sub_via_ffma(b1, x1);
            float sB2 = sub_via_ffma(b2, x2);
            float dB  = (fabsf(sB0) + fabsf(sB1)) + fabsf(sB2);

            float sC0 = sub_via_ffma(c0, x0);
            float sC1 = sub_via_ffma(c1, x1);
            float sC2 = sub_via_ffma(c2, x2);
            float dC  = (fabsf(sC0) + fabsf(sC1)) + fabsf(sC2);

            float sD0 = sub_via_ffma(e0, x0);
            float sD1 = sub_via_ffma(e1, x1);
            float sD2 = sub_via_ffma(e2, x2);
            float dD  = (fabsf(sD0) + fabsf(sD1)) + fabsf(sD2);

            m0 = fminf(m0, dA);
            m1 = fminf(m1, dB);
            m2 = fminf(m2, dC);
            m3 = fminf(m3, dD);
        }
    }

    // Deterministic per-block partial sum of the 128 per-point minima
    float m = fminf(fminf(m0, m1), fminf(m2, m3));
    #pragma unroll
    for (int o = 16; o > 0; o >>= 1)
        m += __shfl_down_sync(0xffffffffu, m, o);
    if ((threadIdx.x & 31) == 0) warp_s[threadIdx.x >> 5] = m;
    __syncthreads();
    if (threadIdx.x == 0) {
        int flat = blockIdx.x + NBLK_X * (blockIdx.y + BATCH * blockIdx.z);
        g_partial[flat] = (warp_s[0] + warp_s[1]) + (warp_s[2] + warp_s[3]);
    }
}

// Sum 512 partials -> mean_x + mean_y (uniform sizes: flat mean over B*N each)
__global__ void chamfer_reduce_kernel(float* __restrict__ out) {
    __shared__ float warp_s[8];
    const int tid = threadIdx.x;          // 256 threads

    float s = 0.0f;
    #pragma unroll
    for (int k = 0; k < NPART / 256; k++)
        s += g_partial[tid + 256 * k];

    #pragma unroll
    for (int o = 16; o > 0; o >>= 1)
        s += __shfl_down_sync(0xffffffffu, s, o);
    if ((tid & 31) == 0) warp_s[tid >> 5] = s;
    __syncthreads();

    if (tid < 32) {
        float v = (tid < 8) ? warp_s[tid] : 0.0f;
        #pragma unroll
        for (int o = 4; o > 0; o >>= 1)
            v += __shfl_down_sync(0xffffffffu, v, o);
        if (tid == 0)
            out[0] = v * (1.0f / (float)(BATCH * NPTS));
    }
}

extern "C" void kernel_launch(void* const* d_in, const int* in_sizes, int n_in,
                              void* d_out, int out_size) {
    const float* x = (const float*)d_in[0];
    const float* y = (const float*)d_in[1];
    float* out = (float*)d_out;
    (void)in_sizes; (void)n_in; (void)out_size;

    dim3 grid(NBLK_X, BATCH, 2);          // 512 blocks of 128 threads
    chamfer_pass_kernel<<<grid, THREADS>>>(x, y);
    chamfer_reduce_kernel<<<1, 256>>>(out);
}

// round 7
// speedup vs baseline: 7.5383x; 1.2144x over previous
#include <cuda_runtime.h>

// Problem constants (fixed by the reference: B=8, N=M=4096, C=3)
#define BATCH   8
#define NPTS    4096
#define TILE    1024
#define THREADS 64
#define NBLK_X  (NPTS / THREADS)            // 64
#define NPART   (NBLK_X * BATCH * 2)        // 1024 per-block partials

__device__ float g_partial[NPART];

// Packed double-pumped FP32 add: r[i] = a[i] + b[i] for two lanes.
// mov.b64 {lo,hi} is register-pair aliasing; ptxas usually elides the MOVs.
__device__ __forceinline__ void addx2(float& r0, float& r1,
                                      float a0, float a1,
                                      float b0, float b1) {
    asm("{\n\t"
        ".reg .b64 A, B, R;\n\t"
        "mov.b64 A, {%2, %3};\n\t"
        "mov.b64 B, {%4, %5};\n\t"
        "add.rn.f32x2 R, A, B;\n\t"
        "mov.b64 {%0, %1}, R;\n\t"
        "}"
        : "=f"(r0), "=f"(r1)
        : "f"(a0), "f"(a1), "f"(b0), "f"(b1));
}

// L1 distance via exact identity |a|+|b| = max(|a+b|, |a-b|):
//   d(x,y) = max(|(x0+x1)-(y0+y1)|, |(x0-x1)-(y0-y1)|) + |x2-y2|
// Targets staged in smem as NEGATED rotated coords (SoA), so every subtraction
// is a packed add. Per 2 pairs: 3 ADD2 + 2 FMNMX(max,|.|) + 2 FADD + 2 FMNMX(min).
__global__ __launch_bounds__(THREADS)
void chamfer_pass_kernel(const float* __restrict__ x,
                         const float* __restrict__ y) {
    __shared__ float svp[TILE];      // -(y0+y1)
    __shared__ float svm[TILE];      // -(y0-y1)
    __shared__ float svz[TILE];      // -y2
    __shared__ float warp_s[THREADS / 32];

    const int b   = blockIdx.y;
    const int dir = blockIdx.z;
    const float* A    = dir == 0 ? x : y;
    const float* Bset = dir == 0 ? y : x;

    const int i = blockIdx.x * THREADS + threadIdx.x;
    const float* Ab = A    + ((size_t)b * NPTS + i) * 3;
    const float* Bb = Bset + (size_t)b * NPTS * 3;

    const float x0 = Ab[0], x1 = Ab[1], x2 = Ab[2];
    const float up = x0 + x1;        // u+
    const float um = x0 - x1;        // u-
    const float uz = x2;

    float m0 = 1e30f, m1 = 1e30f, m2 = 1e30f, m3 = 1e30f;

    for (int t = 0; t < NPTS; t += TILE) {
        __syncthreads();
        for (int k = threadIdx.x; k < TILE; k += THREADS) {
            const float* p = Bb + (size_t)(t + k) * 3;
            float y0 = p[0], y1 = p[1], y2 = p[2];
            svp[k] = -(y0 + y1);
            svm[k] = -(y0 - y1);
            svz[k] = -y2;
        }
        __syncthreads();

        #pragma unroll 4
        for (int j = 0; j < TILE; j += 4) {
            // LDS.64 broadcasts (all lanes same address)
            float2 vpA = *(const float2*)&svp[j];
            float2 vmA = *(const float2*)&svm[j];
            float2 vzA = *(const float2*)&svz[j];
            float2 vpB = *(const float2*)&svp[j + 2];
            float2 vmB = *(const float2*)&svm[j + 2];
            float2 vzB = *(const float2*)&svz[j + 2];

            float sp0, sp1, sm0, sm1, sz0, sz1;
            addx2(sp0, sp1, up, up, vpA.x, vpA.y);
            addx2(sm0, sm1, um, um, vmA.x, vmA.y);
            addx2(sz0, sz1, uz, uz, vzA.x, vzA.y);
            float d0 = fmaxf(fabsf(sp0), fabsf(sm0)) + fabsf(sz0);
            float d1 = fmaxf(fabsf(sp1), fabsf(sm1)) + fabsf(sz1);

            float tp0, tp1, tm0, tm1, tz0, tz1;
            addx2(tp0, tp1, up, up, vpB.x, vpB.y);
            addx2(tm0, tm1, um, um, vmB.x, vmB.y);
            addx2(tz0, tz1, uz, uz, vzB.x, vzB.y);
            float d2 = fmaxf(fabsf(tp0), fabsf(tm0)) + fabsf(tz0);
            float d3 = fmaxf(fabsf(tp1), fabsf(tm1)) + fabsf(tz1);

            m0 = fminf(m0, d0);
            m1 = fminf(m1, d1);
            m2 = fminf(m2, d2);
            m3 = fminf(m3, d3);
        }
    }

    // Deterministic per-block partial sum of the 64 per-point minima
    float m = fminf(fminf(m0, m1), fminf(m2, m3));
    #pragma unroll
    for (int o = 16; o > 0; o >>= 1)
        m += __shfl_down_sync(0xffffffffu, m, o);
    if ((threadIdx.x & 31) == 0) warp_s[threadIdx.x >> 5] = m;
    __syncthreads();
    if (threadIdx.x == 0) {
        int flat = blockIdx.x + NBLK_X * (blockIdx.y + BATCH * blockIdx.z);
        g_partial[flat] = warp_s[0] + warp_s[1];
    }
}

// Sum 1024 partials -> mean_x + mean_y (uniform sizes: flat mean over B*N each)
__global__ void chamfer_reduce_kernel(float* __restrict__ out) {
    __shared__ float warp_s[8];
    const int tid = threadIdx.x;          // 256 threads

    float s = 0.0f;
    #pragma unroll
    for (int k = 0; k < NPART / 256; k++)
        s += g_partial[tid + 256 * k];

    #pragma unroll
    for (int o = 16; o > 0; o >>= 1)
        s += __shfl_down_sync(0xffffffffu, s, o);
    if ((tid & 31) == 0) warp_s[tid >> 5] = s;
    __syncthreads();

    if (tid < 32) {
        float v = (tid < 8) ? warp_s[tid] : 0.0f;
        #pragma unroll
        for (int o = 4; o > 0; o >>= 1)
            v += __shfl_down_sync(0xffffffffu, v, o);
        if (tid == 0)
            out[0] = v * (1.0f / (float)(BATCH * NPTS));
    }
}

extern "C" void kernel_launch(void* const* d_in, const int* in_sizes, int n_in,
                              void* d_out, int out_size) {
    const float* x = (const float*)d_in[0];
    const float* y = (const float*)d_in[1];
    float* out = (float*)d_out;
    (void)in_sizes; (void)n_in; (void)out_size;

    dim3 grid(NBLK_X, BATCH, 2);          // 1024 blocks of 64 threads
    chamfer_pass_kernel<<<grid, THREADS>>>(x, y);
    chamfer_reduce_kernel<<<1, 256>>>(out);
}

// round 11
// speedup vs baseline: 8.8684x; 1.1764x over previous
#include <cuda_runtime.h>

// Problem constants (fixed by the reference: B=8, N=M=4096, C=3)
#define BATCH   8
#define NPTS    4096
#define TILE    1024
#define THREADS 256
#define TI      16            // x-groups per block (lanes 0..15 of each half-warp)
#define TJ      16            // y-groups per block (tid >> 4)
#define XPT     8             // x points per thread
#define XBLK    (TI * XPT)    // 128 x points per block
#define NBX     (NPTS / XBLK) // 32 blocks per batch

// Scratch (no device allocs): per-(batch,block) col-min, partial sums
__device__ float g_colmin[BATCH * NBX * NPTS];     // 4 MB
__device__ float g_rowpart[BATCH * NBX];           // 256
__device__ float g_part2[128];

// Fused pass: each distance computed ONCE, feeds both the x->y row-min and
// the y->x col-min.  L1 via exact identity |a|+|b| = max(|a+b|,|a-b|):
//   d = max(|P_x - P_y|, |M_x - M_y|) + |Z_x - Z_y|,  P=x0+x1, M=x0-x1, Z=x2
// (4 FADD on fma pipe + 2-3 FMNMX on alu pipe per pair).
__global__ __launch_bounds__(THREADS, 2)
void chamfer_fused_kernel(const float* __restrict__ x,
                          const float* __restrict__ y) {
    __shared__ float svp[TILE], svm[TILE], svz[TILE];   // negated target coords
    __shared__ float rm[TJ][XBLK + 1];                  // row-min cross-tj scratch
    __shared__ float warp_s[THREADS / 32];
    const unsigned FULL = 0xffffffffu;

    const int b  = blockIdx.y;
    const int bx = blockIdx.x;
    const int tid = threadIdx.x;
    const int ti = tid & (TI - 1);
    const int tj = tid >> 4;

    // Register-resident transformed coords for this thread's 8 x points
    const float* Xb = x + ((size_t)b * NPTS + bx * XBLK + ti * XPT) * 3;
    float xp[XPT], xm[XPT], xz[XPT], row[XPT];
    #pragma unroll
    for (int k = 0; k < XPT; k++) {
        float a0 = Xb[3 * k], a1 = Xb[3 * k + 1], a2 = Xb[3 * k + 2];
        xp[k] = a0 + a1;
        xm[k] = a0 - a1;
        xz[k] = a2;
        row[k] = 1e30f;
    }

    const float* Yb = y + (size_t)b * NPTS * 3;
    const size_t colbase = ((size_t)(b * NBX + bx)) * NPTS;

    for (int tile = 0; tile < NPTS; tile += TILE) {
        __syncthreads();
        for (int k = tid; k < TILE; k += THREADS) {
            const float* p = Yb + (size_t)(tile + k) * 3;
            float y0 = p[0], y1 = p[1], y2 = p[2];
            svp[k] = -(y0 + y1);
            svm[k] = -(y0 - y1);
            svz[k] = -y2;
        }
        __syncthreads();

        #pragma unroll 2
        for (int jj = 0; jj < TILE / TJ; jj++) {
            const int j = jj * TJ + tj;
            // 2 distinct addresses per warp (tj pair), adjacent -> conflict-free
            float yp = svp[j], ym = svm[j], yz = svz[j];

            float d[XPT];
            #pragma unroll
            for (int k = 0; k < XPT; k++) {
                float sp = xp[k] + yp;
                float sm = xm[k] + ym;
                float sz = xz[k] + yz;
                d[k] = fmaxf(fabsf(sp), fabsf(sm)) + fabsf(sz);
                row[k] = fminf(row[k], d[k]);
            }
            // col-min over this thread's 8 x (explicit tree)
            float c01 = fminf(d[0], d[1]), c23 = fminf(d[2], d[3]);
            float c45 = fminf(d[4], d[5]), c67 = fminf(d[6], d[7]);
            float cmin = fminf(fminf(c01, c23), fminf(c45, c67));
            // min across the 16 ti-lanes (xor of bits 0-3 stays in the half-warp)
            #pragma unroll
            for (int o = 1; o < TI; o <<= 1)
                cmin = fminf(cmin, __shfl_xor_sync(FULL, cmin, o));
            if (ti == 0)
                g_colmin[colbase + tile + j] = cmin;   // lanes 0,16: adjacent j
        }
    }

    // Row-min: combine across the 16 tj groups, then block-sum the 128 mins
    #pragma unroll
    for (int k = 0; k < XPT; k++)
        rm[tj][ti * XPT + k] = row[k];
    __syncthreads();

    float v = 0.0f;
    if (tid < XBLK) {
        float m = rm[0][tid];
        #pragma unroll
        for (int t = 1; t < TJ; t++)
            m = fminf(m, rm[t][tid]);
        v = m;
    }
    #pragma unroll
    for (int o = 16; o > 0; o >>= 1)
        v += __shfl_down_sync(FULL, v, o);
    if ((tid & 31) == 0) warp_s[tid >> 5] = v;
    __syncthreads();
    if (tid == 0) {
        float s = 0.0f;
        #pragma unroll
        for (int w = 0; w < THREADS / 32; w++) s += warp_s[w];
        g_rowpart[b * NBX + bx] = s;   // only warps 0-3 contributed nonzero
    }
}

// Combine per-block col-mins: for each (b, j) take min over the 32 x-blocks,
// then per-block partial sums. Fully coalesced; deterministic order.
__global__ __launch_bounds__(256)
void colmin_combine_kernel() {
    __shared__ float warp_s[8];
    const int idx = blockIdx.x * 256 + threadIdx.x;     // 0..32767
    const int b = idx >> 12, j = idx & (NPTS - 1);

    const float* base = g_colmin + (size_t)b * NBX * NPTS + j;
    float m = base[0];
    #pragma unroll
    for (int bx = 1; bx < NBX; bx++)
        m = fminf(m, base[(size_t)bx * NPTS]);

    #pragma unroll
    for (int o = 16; o > 0; o >>= 1)
        m += __shfl_down_sync(0xffffffffu, m, o);
    if ((threadIdx.x & 31) == 0) warp_s[threadIdx.x >> 5] = m;
    __syncthreads();
    if (threadIdx.x == 0) {
        float s = 0.0f;
        #pragma unroll
        for (int w = 0; w < 8; w++) s += warp_s[w];
        g_part2[blockIdx.x] = s;
    }
}

// total = (sum row-mins + sum col-mins) / (B*N)  ==  mean_x + mean_y  (N == M)
__global__ void final_reduce_kernel(float* __restrict__ out) {
    __shared__ float warp_s[8];
    const int tid = threadIdx.x;   // 256

    float s = g_rowpart[tid] + (tid < 128 ? g_part2[tid] : 0.0f);

    #pragma unroll
    for (int o = 16; o > 0; o >>= 1)
        s += __shfl_down_sync(0xffffffffu, s, o);
    if ((tid & 31) == 0) warp_s[tid >> 5] = s;
    __syncthreads();
    if (tid < 32) {
        float v = (tid < 8) ? warp_s[tid] : 0.0f;
        #pragma unroll
        for (int o = 4; o > 0; o >>= 1)
            v += __shfl_down_sync(0xffffffffu, v, o);
        if (tid == 0)
            out[0] = v * (1.0f / (float)(BATCH * NPTS));
    }
}

extern "C" void kernel_launch(void* const* d_in, const int* in_sizes, int n_in,
                              void* d_out, int out_size) {
    const float* x = (const float*)d_in[0];
    const float* y = (const float*)d_in[1];
    float* out = (float*)d_out;
    (void)in_sizes; (void)n_in; (void)out_size;

    dim3 grid(NBX, BATCH);                 // 32 x 8 = 256 blocks of 256 threads
    chamfer_fused_kernel<<<grid, THREADS>>>(x, y);
    colmin_combine_kernel<<<128, 256>>>();
    final_reduce_kernel<<<1, 256>>>(out);
}

// round 12
// speedup vs baseline: 9.9652x; 1.1237x over previous
#include <cuda_runtime.h>

// Problem constants (fixed by the reference: B=8, N=M=4096, C=3)
#define BATCH   8
#define NPTS    4096
#define THREADS 256
#define TI      16            // x-groups (lanes 0..15 of each half-warp)
#define TJ      16            // y per block-iteration
#define XPT     8             // x points per thread
#define XBLK    (TI * XPT)    // 128 x points per block
#define NBX     (NPTS / XBLK) // 32
#define JSPLIT  4
#define JTILE   (NPTS / JSPLIT)   // 1024 y per block

// Scratch (no device allocs)
__device__ float g_colmin[BATCH * NBX * NPTS];       // 4 MB  [b][bx][j]
__device__ float g_rowmin[BATCH * JSPLIT * NPTS];    // 512KB [b][jq][i]
__device__ float g_part2[128];

// Fused pass: each distance computed ONCE, feeds both reductions.
// L1 via exact identity |a|+|b| = max(|a+b|,|a-b|):
//   d = max(|P_x-P_y|, |M_x-M_y|) + |Z_x-Z_y|,  P=x0+x1, M=x0-x1, Z=x2
__global__ __launch_bounds__(THREADS, 3)
void chamfer_fused_kernel(const float* __restrict__ x,
                          const float* __restrict__ y) {
    __shared__ float svp[JTILE], svm[JTILE], svz[JTILE];  // negated target coords
    __shared__ float rm[TJ][XBLK + 1];                    // row-min cross-tj scratch
    const unsigned FULL = 0xffffffffu;

    const int b  = blockIdx.y;
    const int bx = blockIdx.x;
    const int jq = blockIdx.z;
    const int j0 = jq * JTILE;
    const int tid = threadIdx.x;
    const int ti = tid & (TI - 1);
    const int tj = tid >> 4;

    // Register-resident transformed coords for this thread's 8 x points
    const float* Xb = x + ((size_t)b * NPTS + bx * XBLK + ti * XPT) * 3;
    float xp[XPT], xm[XPT], xz[XPT], row[XPT];
    #pragma unroll
    for (int k = 0; k < XPT; k++) {
        float a0 = Xb[3 * k], a1 = Xb[3 * k + 1], a2 = Xb[3 * k + 2];
        xp[k] = a0 + a1;
        xm[k] = a0 - a1;
        xz[k] = a2;
        row[k] = 1e30f;
    }

    // Stage this block's y quarter (negated rotated coords, SoA)
    const float* Yb = y + ((size_t)b * NPTS + j0) * 3;
    for (int k = tid; k < JTILE; k += THREADS) {
        const float* p = Yb + (size_t)k * 3;
        float y0 = p[0], y1 = p[1], y2 = p[2];
        svp[k] = -(y0 + y1);
        svm[k] = -(y0 - y1);
        svz[k] = -y2;
    }
    __syncthreads();

    float* colout = g_colmin + ((size_t)(b * NBX + bx)) * NPTS + j0;

    #pragma unroll 2
    for (int jj = 0; jj < JTILE / TJ; jj++) {
        const int j = jj * TJ + tj;
        float yp = svp[j], ym = svm[j], yz = svz[j];

        float d[XPT];
        #pragma unroll
        for (int k = 0; k < XPT; k++) {
            float sp = xp[k] + yp;
            float sm = xm[k] + ym;
            float sz = xz[k] + yz;
            d[k] = fmaxf(fabsf(sp), fabsf(sm)) + fabsf(sz);
            row[k] = fminf(row[k], d[k]);
        }
        // col-min over this thread's 8 x (explicit tree)
        float c01 = fminf(d[0], d[1]), c23 = fminf(d[2], d[3]);
        float c45 = fminf(d[4], d[5]), c67 = fminf(d[6], d[7]);
        float cmin = fminf(fminf(c01, c23), fminf(c45, c67));
        // min across the 16 ti-lanes (xor of bits 0-3 stays in the half-warp)
        #pragma unroll
        for (int o = 1; o < TI; o <<= 1)
            cmin = fminf(cmin, __shfl_xor_sync(FULL, cmin, o));
        if (ti == 0)
            colout[j] = cmin;          // lanes 0,16 write adjacent j
    }

    // Row-min: combine across the 16 tj groups, write per-x (min over jq later)
    #pragma unroll
    for (int k = 0; k < XPT; k++)
        rm[tj][ti * XPT + k] = row[k];
    __syncthreads();

    if (tid < XBLK) {
        float m = rm[0][tid];
        #pragma unroll
        for (int t = 1; t < TJ; t++)
            m = fminf(m, rm[t][tid]);
        g_rowmin[((size_t)(b * JSPLIT + jq)) * NPTS + bx * XBLK + tid] = m;
    }
}

// Combine: per (b,i)  col-min over 32 x-blocks  +  row-min over 4 j-quarters,
// then per-block partial sums. Fixed order -> deterministic.
__global__ __launch_bounds__(256)
void combine_kernel() {
    __shared__ float warp_s[8];
    const int idx = blockIdx.x * 256 + threadIdx.x;     // 0..32767
    const int b = idx >> 12, i = idx & (NPTS - 1);

    const float* cbase = g_colmin + (size_t)b * NBX * NPTS + i;
    float cm = cbase[0];
    #pragma unroll
    for (int bx = 1; bx < NBX; bx++)
        cm = fminf(cm, cbase[(size_t)bx * NPTS]);

    const float* rbase = g_rowmin + (size_t)b * JSPLIT * NPTS + i;
    float rv = rbase[0];
    #pragma unroll
    for (int q = 1; q < JSPLIT; q++)
        rv = fminf(rv, rbase[(size_t)q * NPTS]);

    float s = cm + rv;
    #pragma unroll
    for (int o = 16; o > 0; o >>= 1)
        s += __shfl_down_sync(0xffffffffu, s, o);
    if ((threadIdx.x & 31) == 0) warp_s[threadIdx.x >> 5] = s;
    __syncthreads();
    if (threadIdx.x == 0) {
        float t = 0.0f;
        #pragma unroll
        for (int w = 0; w < 8; w++) t += warp_s[w];
        g_part2[blockIdx.x] = t;
    }
}

// total = (sum row-mins + sum col-mins) / (B*N)  ==  mean_x + mean_y  (N == M)
__global__ void final_reduce_kernel(float* __restrict__ out) {
    __shared__ float warp_s[4];
    const int tid = threadIdx.x;   // 128

    float s = g_part2[tid];
    #pragma unroll
    for (int o = 16; o > 0; o >>= 1)
        s += __shfl_down_sync(0xffffffffu, s, o);
    if ((tid & 31) == 0) warp_s[tid >> 5] = s;
    __syncthreads();
    if (tid == 0)
        out[0] = (warp_s[0] + warp_s[1] + warp_s[2] + warp_s[3])
                 * (1.0f / (float)(BATCH * NPTS));
}

extern "C" void kernel_launch(void* const* d_in, const int* in_sizes, int n_in,
                              void* d_out, int out_size) {
    const float* x = (const float*)d_in[0];
    const float* y = (const float*)d_in[1];
    float* out = (float*)d_out;
    (void)in_sizes; (void)n_in; (void)out_size;

    dim3 grid(NBX, BATCH, JSPLIT);         // 32 x 8 x 4 = 1024 blocks
    chamfer_fused_kernel<<<grid, THREADS>>>(x, y);
    combine_kernel<<<128, 256>>>();
    final_reduce_kernel<<<1, 128>>>(out);
}

// round 13
// speedup vs baseline: 10.7828x; 1.0820x over previous
#include <cuda_runtime.h>

// Problem constants (fixed by the reference: B=8, N=M=4096, C=3)
#define BATCH   8
#define NPTS    4096
#define THREADS 256
#define TI      16            // x-groups (lanes 0..15 of each half-warp)
#define TJ      16            // y-groups; each handles 4 consecutive j per iter
#define XPT     8             // x points per thread
#define XBLK    (TI * XPT)    // 128 x points per block
#define NBX     (NPTS / XBLK) // 32
#define JSPLIT  4
#define JTILE   (NPTS / JSPLIT)   // 1024 y per block
#define JSTEP   (TJ * 4)          // 64 j consumed per iteration

// Scratch (no device allocs)
__device__ float g_colmin[BATCH * NBX * NPTS];       // 4 MB  [b][bx][j]
__device__ float g_rowmin[BATCH * JSPLIT * NPTS];    // 512KB [b][jq][i]
__device__ float g_part2[128];

// Fused pass: each distance computed ONCE, feeds both reductions.
// L1 via exact identity |a|+|b| = max(|a+b|,|a-b|):
//   d = max(|P_x-P_y|, |M_x-M_y|) + |Z_x-Z_y|,  P=x0+x1, M=x0-x1, Z=x2
__global__ __launch_bounds__(THREADS, 3)
void chamfer_fused_kernel(const float* __restrict__ x,
                          const float* __restrict__ y) {
    __shared__ float svp[JTILE], svm[JTILE], svz[JTILE];  // negated target coords
    __shared__ float rm[TJ][XBLK + 1];                    // row-min cross-tj scratch
    const unsigned FULL = 0xffffffffu;

    const int b  = blockIdx.y;
    const int bx = blockIdx.x;
    const int jq = blockIdx.z;
    const int j0 = jq * JTILE;
    const int tid = threadIdx.x;
    const int ti = tid & (TI - 1);
    const int tj = tid >> 4;

    // Register-resident transformed coords for this thread's 8 x points
    const float* Xb = x + ((size_t)b * NPTS + bx * XBLK + ti * XPT) * 3;
    float xp[XPT], xm[XPT], xz[XPT], row[XPT];
    #pragma unroll
    for (int k = 0; k < XPT; k++) {
        float a0 = Xb[3 * k], a1 = Xb[3 * k + 1], a2 = Xb[3 * k + 2];
        xp[k] = a0 + a1;
        xm[k] = a0 - a1;
        xz[k] = a2;
        row[k] = 1e30f;
    }

    // Stage this block's y quarter (negated rotated coords, SoA)
    const float* Yb = y + ((size_t)b * NPTS + j0) * 3;
    for (int k = tid; k < JTILE; k += THREADS) {
        const float* p = Yb + (size_t)k * 3;
        float y0 = p[0], y1 = p[1], y2 = p[2];
        svp[k] = -(y0 + y1);
        svm[k] = -(y0 - y1);
        svz[k] = -y2;
    }
    __syncthreads();

    float* colout = g_colmin + ((size_t)(b * NBX + bx)) * NPTS + j0;

    // 16 iterations; each thread handles 4 consecutive j via LDS.128
    for (int jj = 0; jj < JTILE / JSTEP; jj++) {
        const int jb = jj * JSTEP + tj * 4;
        // Warp touches 2 consecutive 16B lines -> conflict-free broadcast
        float4 vp = *(const float4*)&svp[jb];
        float4 vm = *(const float4*)&svm[jb];
        float4 vz = *(const float4*)&svz[jb];

        float cm[4];
        #pragma unroll
        for (int jc = 0; jc < 4; jc++) {
            float yp = jc == 0 ? vp.x : jc == 1 ? vp.y : jc == 2 ? vp.z : vp.w;
            float ym = jc == 0 ? vm.x : jc == 1 ? vm.y : jc == 2 ? vm.z : vm.w;
            float yz = jc == 0 ? vz.x : jc == 1 ? vz.y : jc == 2 ? vz.z : vz.w;

            float d[XPT];
            #pragma unroll
            for (int k = 0; k < XPT; k++) {
                float sp = xp[k] + yp;
                float sm = xm[k] + ym;
                float sz = xz[k] + yz;
                d[k] = fmaxf(fabsf(sp), fabsf(sm)) + fabsf(sz);
                row[k] = fminf(row[k], d[k]);
            }
            // col-min over this thread's 8 x (explicit tree)
            float c01 = fminf(d[0], d[1]), c23 = fminf(d[2], d[3]);
            float c45 = fminf(d[4], d[5]), c67 = fminf(d[6], d[7]);
            float cmin = fminf(fminf(c01, c23), fminf(c45, c67));
            // min across the 16 ti-lanes (xor of bits 0-3 stays in half-warp)
            #pragma unroll
            for (int o = 1; o < TI; o <<= 1)
                cmin = fminf(cmin, __shfl_xor_sync(FULL, cmin, o));
            cm[jc] = cmin;
        }
        if (ti == 0)   // 2 lanes/warp write adjacent float4s -> coalesced 32B
            *(float4*)&colout[jb] = make_float4(cm[0], cm[1], cm[2], cm[3]);
    }

    // Row-min: combine across the 16 tj groups, write per-x (min over jq later)
    #pragma unroll
    for (int k = 0; k < XPT; k++)
        rm[tj][ti * XPT + k] = row[k];
    __syncthreads();

    if (tid < XBLK) {
        float m = rm[0][tid];
        #pragma unroll
        for (int t = 1; t < TJ; t++)
            m = fminf(m, rm[t][tid]);
        g_rowmin[((size_t)(b * JSPLIT + jq)) * NPTS + bx * XBLK + tid] = m;
    }
}

// Combine: per (b,i)  col-min over 32 x-blocks  +  row-min over 4 j-quarters,
// then per-block partial sums. Fixed order -> deterministic.
__global__ __launch_bounds__(256)
void combine_kernel() {
    __shared__ float warp_s[8];
    const int idx = blockIdx.x * 256 + threadIdx.x;     // 0..32767
    const int b = idx >> 12, i = idx & (NPTS - 1);

    const float* cbase = g_colmin + (size_t)b * NBX * NPTS + i;
    float cm = cbase[0];
    #pragma unroll
    for (int bx = 1; bx < NBX; bx++)
        cm = fminf(cm, cbase[(size_t)bx * NPTS]);

    const float* rbase = g_rowmin + (size_t)b * JSPLIT * NPTS + i;
    float rv = rbase[0];
    #pragma unroll
    for (int q = 1; q < JSPLIT; q++)
        rv = fminf(rv, rbase[(size_t)q * NPTS]);

    float s = cm + rv;
    #pragma unroll
    for (int o = 16; o > 0; o >>= 1)
        s += __shfl_down_sync(0xffffffffu, s, o);
    if ((threadIdx.x & 31) == 0) warp_s[threadIdx.x >> 5] = s;
    __syncthreads();
    if (threadIdx.x == 0) {
        float t = 0.0f;
        #pragma unroll
        for (int w = 0; w < 8; w++) t += warp_s[w];
        g_part2[blockIdx.x] = t;
    }
}

// total = (sum row-mins + sum col-mins) / (B*N)  ==  mean_x + mean_y  (N == M)
__global__ void final_reduce_kernel(float* __restrict__ out) {
    __shared__ float warp_s[4];
    const int tid = threadIdx.x;   // 128

    float s = g_part2[tid];
    #pragma unroll
    for (int o = 16; o > 0; o >>= 1)
        s += __shfl_down_sync(0xffffffffu, s, o);
    if ((tid & 31) == 0) warp_s[tid >> 5] = s;
    __syncthreads();
    if (tid == 0)
        out[0] = (warp_s[0] + warp_s[1] + warp_s[2] + warp_s[3])
                 * (1.0f / (float)(BATCH * NPTS));
}

extern "C" void kernel_launch(void* const* d_in, const int* in_sizes, int n_in,
                              void* d_out, int out_size) {
    const float* x = (const float*)d_in[0];
    const float* y = (const float*)d_in[1];
    float* out = (float*)d_out;
    (void)in_sizes; (void)n_in; (void)out_size;

    dim3 grid(NBX, BATCH, JSPLIT);         // 32 x 8 x 4 = 1024 blocks
    chamfer_fused_kernel<<<grid, THREADS>>>(x, y);
    combine_kernel<<<128, 256>>>();
    final_reduce_kernel<<<1, 128>>>(out);
}